// round 9
// baseline (speedup 1.0000x reference)
#include <cuda_runtime.h>
#include <cuda_bf16.h>
#include <math.h>
#include <stdint.h>

// ---------------- problem constants ----------------
#define NNODES   100000
#define NEDGES   200000
#define EMBD     300
#define LD       320            // padded feature stride (K and N pad)
#define MPAD     100096         // 782 * 128
#define NGR      4096
#define FEAT     256
#define HFEAT    128
#define NLAYER   5
#define NTILES   98             // ceil(NNODES/1024)

// ---------------- device scratch ----------------
__device__ float g_bufH[(size_t)MPAD * LD];   // aggregate output (fp32)
__device__ float g_bufX[(size_t)MPAD * LD];   // GEMM output (fp32)
__device__ __align__(16) __nv_bfloat16 g_hbf_hi[(size_t)MPAD * LD];  // bf16 split of h
__device__ __align__(16) __nv_bfloat16 g_hbf_lo[(size_t)MPAD * LD];
__device__ __align__(16) __nv_bfloat16 g_wt_hi[NLAYER * LD * LD];    // W^T bf16 split [l][n][k]
__device__ __align__(16) __nv_bfloat16 g_wt_lo[NLAYER * LD * LD];
__device__ float g_colsum[LD];
__device__ float g_colsq[LD];
__device__ int   g_deg[NNODES + 1];
__device__ int   g_rowptr[NNODES + 1];
__device__ int   g_cursor[NNODES];
__device__ int   g_entries[NEDGES];
__device__ int   g_tilesum[NTILES];
__device__ int   g_tileoff[NTILES];
__device__ float g_sums[NGR * EMBD];
__device__ int   g_counts[NGR];
__device__ float g_hg[NGR * EMBD];

// ---------------- helpers ----------------
__device__ __forceinline__ uint32_t smem_u32(const void* p) {
    uint32_t a;
    asm("{ .reg .u64 t; cvta.to.shared.u64 t, %1; cvt.u32.u64 %0, t; }" : "=r"(a) : "l"(p));
    return a;
}

static __device__ __forceinline__ void split_bf16(float x, __nv_bfloat16& hi, __nv_bfloat16& lo) {
    hi = __float2bfloat16(x);
    lo = __float2bfloat16(x - __bfloat162float(hi));
}

__device__ __forceinline__ void ldsm_x4(uint32_t addr, uint32_t* r) {
    asm volatile("ldmatrix.sync.aligned.m8n8.x4.shared.b16 {%0,%1,%2,%3}, [%4];"
                 : "=r"(r[0]), "=r"(r[1]), "=r"(r[2]), "=r"(r[3]) : "r"(addr));
}

__device__ __forceinline__ void mma16816(float* c, const uint32_t* a, const uint32_t* b) {
    asm volatile(
        "mma.sync.aligned.m16n8k16.row.col.f32.bf16.bf16.f32 "
        "{%0,%1,%2,%3}, {%4,%5,%6,%7}, {%8,%9}, {%0,%1,%2,%3};"
        : "+f"(c[0]), "+f"(c[1]), "+f"(c[2]), "+f"(c[3])
        : "r"(a[0]), "r"(a[1]), "r"(a[2]), "r"(a[3]), "r"(b[0]), "r"(b[1]));
}

#define CP16(dst, src) \
    asm volatile("cp.async.cg.shared.global [%0], [%1], 16;" :: "r"(dst), "l"(src))
#define CP_COMMIT() asm volatile("cp.async.commit_group;")
#define CP_WAIT0()  asm volatile("cp.async.wait_group 0;")

// ---------------- embed: bf16 split planes only (zero padding) ----------------
__global__ void embed_kernel(const int* __restrict__ at, const int* __restrict__ ch,
                             const float* __restrict__ e1, const float* __restrict__ e2,
                             int N) {
    int r = blockIdx.x;              // 0..MPAD-1
    int f = threadIdx.x;             // 0..319
    float v = 0.f;
    if (r < N && f < EMBD) {
        v = e1[(size_t)at[r] * EMBD + f] + e2[(size_t)ch[r] * EMBD + f];
    }
    size_t idx = (size_t)r * LD + f;
    __nv_bfloat16 hi, lo;
    split_bf16(v, hi, lo);
    g_hbf_hi[idx] = hi;
    g_hbf_lo[idx] = lo;
}

// ---------------- W^T bf16 split: wt[l][n][k] = split(W[l][k][n]) ----------------
__global__ void conv_w_kernel(const float* __restrict__ W) {
    int n = blockIdx.x, l = blockIdx.y, k = threadIdx.x;   // 320 x 5, 320 threads
    float v = (n < EMBD && k < EMBD) ? W[((size_t)l * EMBD + k) * EMBD + n] : 0.f;
    __nv_bfloat16 hi, lo;
    split_bf16(v, hi, lo);
    size_t idx = ((size_t)l * LD + n) * LD + k;
    g_wt_hi[idx] = hi;
    g_wt_lo[idx] = lo;
}

// ---------------- CSR build ----------------
__global__ void zero_deg_kernel(int N) {
    int i = blockIdx.x * blockDim.x + threadIdx.x;
    if (i <= N) g_deg[i] = 0;
}
__global__ void count_kernel(const int* __restrict__ colp, int E) {
    int e = blockIdx.x * blockDim.x + threadIdx.x;
    if (e < E) atomicAdd(&g_deg[colp[e]], 1);
}
__global__ void scan1_kernel(int N) {
    __shared__ int ws[32];
    int tid = threadIdx.x, lane = tid & 31, w = tid >> 5;
    int i = blockIdx.x * 1024 + tid;
    int v = (i < N) ? g_deg[i] : 0;
    int x = v;
    #pragma unroll
    for (int o = 1; o < 32; o <<= 1) {
        int y = __shfl_up_sync(0xFFFFFFFFu, x, o);
        if (lane >= o) x += y;
    }
    if (lane == 31) ws[w] = x;
    __syncthreads();
    if (w == 0) {
        int t = ws[lane];
        #pragma unroll
        for (int o = 1; o < 32; o <<= 1) {
            int y = __shfl_up_sync(0xFFFFFFFFu, t, o);
            if (lane >= o) t += y;
        }
        ws[lane] = t;
    }
    __syncthreads();
    int incl = x + (w ? ws[w - 1] : 0);
    if (i < N) g_rowptr[i] = incl - v;
    if (tid == 1023) g_tilesum[blockIdx.x] = incl;
}
__global__ void scan2_kernel(int T, int N) {
    __shared__ int ws[4];
    int tid = threadIdx.x, lane = tid & 31, w = tid >> 5;   // 128 threads
    int v = (tid < T) ? g_tilesum[tid] : 0;
    int x = v;
    #pragma unroll
    for (int o = 1; o < 32; o <<= 1) {
        int y = __shfl_up_sync(0xFFFFFFFFu, x, o);
        if (lane >= o) x += y;
    }
    if (lane == 31) ws[w] = x;
    __syncthreads();
    int add = 0;
    for (int j = 0; j < w; j++) add += ws[j];
    int incl = x + add;
    if (tid < T) g_tileoff[tid] = incl - v;
    if (tid == T - 1) g_rowptr[N] = incl;
}
__global__ void scan3_kernel(int N) {
    int i = blockIdx.x * 1024 + threadIdx.x;
    if (i < N) {
        int v = g_rowptr[i] + g_tileoff[blockIdx.x];
        g_rowptr[i] = v;
        g_cursor[i] = v;
    }
}
__global__ void fill_kernel(const int* __restrict__ rowp, const int* __restrict__ colp,
                            const int* __restrict__ et, const int* __restrict__ ed, int E) {
    int e = blockIdx.x * blockDim.x + threadIdx.x;
    if (e >= E) return;
    int c = colp[e];
    int pos = atomicAdd(&g_cursor[c], 1);
    g_entries[pos] = rowp[e] | (et[e] << 20) | (ed[e] << 23);
}

// ---------------- HMMA 3xBF16 GEMM, cp.async double-buffered ----------------
// CTA tile 128x64, BK=32, 8 warps as 4(M)x2(N), warp tile 32x32.
// SMEM rows padded to 40 bf16 (80B) -> conflict-free ldmatrix.
#define ASTR 40
#define STAGE_B 30720
#define AH_OFF 0
#define AL_OFF 10240
#define BH_OFF 20480
#define BL_OFF 25600
#define GEMM_SMEM (2 * STAGE_B)

__global__ __launch_bounds__(256, 2) void hmma_gemm_kernel(int layer) {
    extern __shared__ __align__(16) char dsm[];
    uint32_t sbase = smem_u32(dsm);
    int tid = threadIdx.x, wid = tid >> 5, lane = tid & 31;
    int bm = blockIdx.y * 128, bn = blockIdx.x * 64;
    int wm = (wid & 3) * 32;
    int wn = (wid >> 2) * 32;

    const __nv_bfloat16* Ah = g_hbf_hi + (size_t)bm * LD;
    const __nv_bfloat16* Al = g_hbf_lo + (size_t)bm * LD;
    const __nv_bfloat16* Bh = g_wt_hi + ((size_t)layer * LD + bn) * LD;
    const __nv_bfloat16* Bl = g_wt_lo + ((size_t)layer * LD + bn) * LD;

    float acc[2][4][4];
    #pragma unroll
    for (int i = 0; i < 2; i++)
        #pragma unroll
        for (int j = 0; j < 4; j++)
            #pragma unroll
            for (int q = 0; q < 4; q++) acc[i][j][q] = 0.f;

    // ldmatrix lane addressing (bytes, relative to plane start)
    uint32_t aoff = (uint32_t)((wm + (lane & 15)) * ASTR + (lane >> 4) * 8) * 2;
    uint32_t boff = (uint32_t)((wn + (lane & 7) + ((lane >> 4) & 1) * 8) * ASTR +
                               ((lane >> 3) & 1) * 8) * 2;

    // async-copy addressing
    int ar0 = tid >> 2, ac = tid & 3;                    // A: rows ar0, ar0+64
    uint32_t a_so = (uint32_t)(ar0 * ASTR + ac * 8) * 2;
    uint32_t a_so1 = (uint32_t)((ar0 + 64) * ASTR + ac * 8) * 2;
    uint32_t b_so = a_so;                                 // B: row ar0 (0..63)

    #define GEMM_ISSUE(kc, s) do {                                              \
        uint32_t st_ = sbase + (s) * STAGE_B;                                   \
        int k0_ = (kc) * 32;                                                    \
        const __nv_bfloat16* pa0h = Ah + (size_t)ar0 * LD + k0_ + ac * 8;       \
        const __nv_bfloat16* pa0l = Al + (size_t)ar0 * LD + k0_ + ac * 8;       \
        const __nv_bfloat16* pa1h = pa0h + (size_t)64 * LD;                     \
        const __nv_bfloat16* pa1l = pa0l + (size_t)64 * LD;                     \
        const __nv_bfloat16* pbh  = Bh + (size_t)ar0 * LD + k0_ + ac * 8;       \
        const __nv_bfloat16* pbl  = Bl + (size_t)ar0 * LD + k0_ + ac * 8;       \
        CP16(st_ + AH_OFF + a_so,  pa0h);                                       \
        CP16(st_ + AL_OFF + a_so,  pa0l);                                       \
        CP16(st_ + AH_OFF + a_so1, pa1h);                                       \
        CP16(st_ + AL_OFF + a_so1, pa1l);                                       \
        CP16(st_ + BH_OFF + b_so,  pbh);                                        \
        CP16(st_ + BL_OFF + b_so,  pbl);                                        \
        CP_COMMIT();                                                            \
    } while (0)

    GEMM_ISSUE(0, 0);
    CP_WAIT0();
    __syncthreads();

    for (int kc = 0; kc < 10; kc++) {
        int cur = kc & 1;
        if (kc < 9) GEMM_ISSUE(kc + 1, cur ^ 1);
        uint32_t st = sbase + cur * STAGE_B;

        #pragma unroll
        for (int k16 = 0; k16 < 2; k16++) {
            uint32_t kb = (uint32_t)k16 * 32;
            uint32_t afh[2][4], afl[2][4];
            #pragma unroll
            for (int mi = 0; mi < 2; mi++) {
                uint32_t o = aoff + (uint32_t)(mi * 16 * ASTR) * 2 + kb;
                ldsm_x4(st + AH_OFF + o, afh[mi]);
                ldsm_x4(st + AL_OFF + o, afl[mi]);
            }
            uint32_t bfh[4][2], bfl[4][2];
            #pragma unroll
            for (int nj = 0; nj < 4; nj += 2) {
                uint32_t o = boff + (uint32_t)(nj * 8 * ASTR) * 2 + kb;
                uint32_t t[4];
                ldsm_x4(st + BH_OFF + o, t);
                bfh[nj][0] = t[0]; bfh[nj][1] = t[1];
                bfh[nj + 1][0] = t[2]; bfh[nj + 1][1] = t[3];
                ldsm_x4(st + BL_OFF + o, t);
                bfl[nj][0] = t[0]; bfl[nj][1] = t[1];
                bfl[nj + 1][0] = t[2]; bfl[nj + 1][1] = t[3];
            }
            #pragma unroll
            for (int mi = 0; mi < 2; mi++)
                #pragma unroll
                for (int ni = 0; ni < 4; ni++) {
                    mma16816(acc[mi][ni], afh[mi], bfh[ni]);
                    mma16816(acc[mi][ni], afh[mi], bfl[ni]);
                    mma16816(acc[mi][ni], afl[mi], bfh[ni]);
                }
        }
        if (kc < 9) CP_WAIT0();
        __syncthreads();
    }

    // epilogue
    int qr = lane >> 2, qc = (lane & 3) * 2;
    #pragma unroll
    for (int mi = 0; mi < 2; mi++) {
        int row0 = bm + wm + mi * 16 + qr;
        #pragma unroll
        for (int ni = 0; ni < 4; ni++) {
            int col = bn + wn + ni * 8 + qc;
            float2 v0; v0.x = acc[mi][ni][0]; v0.y = acc[mi][ni][1];
            float2 v1; v1.x = acc[mi][ni][2]; v1.y = acc[mi][ni][3];
            *(float2*)&g_bufX[(size_t)row0 * LD + col] = v0;
            *(float2*)&g_bufX[(size_t)(row0 + 8) * LD + col] = v1;
        }
    }
}

// ---------------- fused aggregation + BN column stats ----------------
// 128 rows per block, 320 column threads; one atomic pair per thread at end.
__global__ __launch_bounds__(320) void aggstats_kernel(
        const float* __restrict__ ee1_l, const float* __restrict__ ee2_l,
        const float* __restrict__ b_l, int N) {
    int f = threadIdx.x;
    bool act = f < EMBD;
    float sl = ee1_l[4] + ee2_l[0];
    float bf = act ? b_l[f] : 0.f;
    int r0 = blockIdx.x * 128;
    int rend = min(r0 + 128, N);
    float s = 0.f, q = 0.f;
    for (int r = r0; r < rend; r++) {
        float acc = g_bufX[(size_t)r * LD + f] + bf + sl;
        int st = g_rowptr[r], en = g_rowptr[r + 1];
        for (int i = st; i < en; i++) {
            int p = g_entries[i];
            float esc = ee1_l[(p >> 20) & 7] + ee2_l[(p >> 23) & 3];
            acc += g_bufX[(size_t)(p & 0xFFFFF) * LD + f] + esc;
        }
        if (act) {
            g_bufH[(size_t)r * LD + f] = acc;
            s += acc;
            q += acc * acc;
        }
    }
    if (act) {
        atomicAdd(&g_colsum[f], s);
        atomicAdd(&g_colsq[f], q);
    }
}

// ---------------- BN stats zero + normalize ----------------
__global__ void zero_stats_kernel() {
    int i = blockIdx.x * blockDim.x + threadIdx.x;
    if (i < LD) { g_colsum[i] = 0.f; g_colsq[i] = 0.f; }
}
__global__ __launch_bounds__(320) void bnnorm_kernel(
        const float* __restrict__ gamma_l, const float* __restrict__ beta_l,
        int N, int do_relu, int wr_f32, int wr_bf16) {
    int f = threadIdx.x;
    if (f >= EMBD) return;
    const float invN = 1.0f / (float)N;
    float mean = g_colsum[f] * invN;
    float var  = g_colsq[f] * invN - mean * mean;
    float scale = gamma_l[f] * rsqrtf(var + 1e-5f);
    float shift = beta_l[f] - mean * scale;
    int r0 = blockIdx.x * 16;
    int rend = min(r0 + 16, N);
    for (int r = r0; r < rend; r++) {
        size_t idx = (size_t)r * LD + f;
        float y = g_bufH[idx] * scale + shift;
        if (do_relu) y = fmaxf(y, 0.f);
        if (wr_f32) g_bufH[idx] = y;
        if (wr_bf16) {
            __nv_bfloat16 hi, lo;
            split_bf16(y, hi, lo);
            g_hbf_hi[idx] = hi;
            g_hbf_lo[idx] = lo;
        }
    }
}

// ---------------- pooling (run-length accumulate, batch is sorted) ----------------
__global__ void zero_pool_kernel() {
    int i = blockIdx.x * blockDim.x + threadIdx.x;
    if (i < NGR * EMBD) g_sums[i] = 0.f;
    if (i < NGR) g_counts[i] = 0;
}
__global__ __launch_bounds__(320) void pool_kernel(const int* __restrict__ batch, int N) {
    int f = threadIdx.x;
    int r0 = blockIdx.x * 128;
    int rend = min(r0 + 128, N);
    if (r0 >= N) return;
    int curg = batch[r0];
    float acc = 0.f;
    int cnt = 0;
    for (int r = r0; r < rend; r++) {
        int g = batch[r];
        if (g != curg) {
            if (f < EMBD && acc != 0.f) atomicAdd(&g_sums[(size_t)curg * EMBD + f], acc);
            else if (f < EMBD) atomicAdd(&g_sums[(size_t)curg * EMBD + f], acc);
            if (f == EMBD) atomicAdd(&g_counts[curg], cnt);
            curg = g; acc = 0.f; cnt = 0;
        }
        if (f < EMBD) acc += g_bufH[(size_t)r * LD + f];
        cnt++;
    }
    if (f < EMBD) atomicAdd(&g_sums[(size_t)curg * EMBD + f], acc);
    if (f == EMBD) atomicAdd(&g_counts[curg], cnt);
}
__global__ __launch_bounds__(320) void hg_kernel() {
    int g = blockIdx.x;
    int t = threadIdx.x;
    if (t >= EMBD) return;
    float cnt = fmaxf((float)g_counts[g], 1.0f);
    g_hg[(size_t)g * EMBD + t] = g_sums[(size_t)g * EMBD + t] / cnt;
}

// ---------------- hf = hg @ feat_W + feat_b ----------------
__global__ __launch_bounds__(256) void featgemm_kernel(
        const float* __restrict__ fw, const float* __restrict__ fb,
        float* __restrict__ hf) {
    __shared__ __align__(16) float s[8 * EMBD];
    int g0 = blockIdx.x * 8;
    int j = threadIdx.x;  // 0..255
    for (int idx = j; idx < 8 * EMBD; idx += 256)
        s[idx] = g_hg[(size_t)g0 * EMBD + idx];
    __syncthreads();
    float acc[8];
    float bb = fb[j];
    #pragma unroll
    for (int i = 0; i < 8; i++) acc[i] = bb;
    for (int k = 0; k < EMBD; k++) {
        float w = fw[k * FEAT + j];
        #pragma unroll
        for (int i = 0; i < 8; i++) acc[i] = fmaf(s[i * EMBD + k], w, acc[i]);
    }
    #pragma unroll
    for (int i = 0; i < 8; i++)
        hf[(size_t)(g0 + i) * FEAT + j] = acc[i];
}

// ---------------- head: pred = softplus(hf@W1+b1)@W2 + b2 ----------------
__device__ __forceinline__ float softplus_f(float x) {
    return fmaxf(x, 0.f) + log1pf(expf(-fabsf(x)));
}
__global__ __launch_bounds__(128) void head_kernel(
        const float* __restrict__ hf,
        const float* __restrict__ W1, const float* __restrict__ b1,
        const float* __restrict__ W2, const float* __restrict__ b2,
        float* __restrict__ pred) {
    __shared__ __align__(16) float s[8 * FEAT];
    __shared__ float redA[8][4], redB[8][4];
    int g0 = blockIdx.x * 8;
    int j = threadIdx.x;  // 0..127
    for (int idx = j; idx < 8 * FEAT; idx += 128)
        s[idx] = hf[(size_t)g0 * FEAT + idx];
    __syncthreads();
    float acc[8];
    float bb = b1[j];
    #pragma unroll
    for (int i = 0; i < 8; i++) acc[i] = bb;
    for (int k = 0; k < FEAT; k++) {
        float w = W1[k * HFEAT + j];
        #pragma unroll
        for (int i = 0; i < 8; i++) acc[i] = fmaf(s[i * FEAT + k], w, acc[i]);
    }
    float w0 = W2[j * 2], w1 = W2[j * 2 + 1];
    int lane = j & 31, wid = j >> 5;
    #pragma unroll
    for (int i = 0; i < 8; i++) {
        float tv = softplus_f(acc[i]);
        float v0 = tv * w0, v1 = tv * w1;
        #pragma unroll
        for (int off = 16; off > 0; off >>= 1) {
            v0 += __shfl_down_sync(0xFFFFFFFFu, v0, off);
            v1 += __shfl_down_sync(0xFFFFFFFFu, v1, off);
        }
        if (lane == 0) { redA[i][wid] = v0; redB[i][wid] = v1; }
    }
    __syncthreads();
    if (j < 8) {
        float p0 = redA[j][0] + redA[j][1] + redA[j][2] + redA[j][3] + b2[0];
        float p1 = redB[j][0] + redB[j][1] + redB[j][2] + redB[j][3] + b2[1];
        pred[(size_t)(g0 + j) * 2 + 0] = p0;
        pred[(size_t)(g0 + j) * 2 + 1] = p1;
    }
}

// ---------------- launch ----------------
extern "C" void kernel_launch(void* const* d_in, const int* in_sizes, int n_in,
                              void* d_out, int out_size) {
    const int*   atom_type = (const int*)d_in[0];
    const int*   chirality = (const int*)d_in[1];
    const int*   edge_index = (const int*)d_in[2];
    const int*   edge_type = (const int*)d_in[3];
    const int*   edge_dir  = (const int*)d_in[4];
    const int*   batch     = (const int*)d_in[5];
    const float* atom_emb1 = (const float*)d_in[6];
    const float* atom_emb2 = (const float*)d_in[7];
    const float* W         = (const float*)d_in[8];
    const float* b         = (const float*)d_in[9];
    const float* ee1       = (const float*)d_in[10];
    const float* ee2       = (const float*)d_in[11];
    const float* bn_gamma  = (const float*)d_in[12];
    const float* bn_beta   = (const float*)d_in[13];
    const float* feat_W    = (const float*)d_in[14];
    const float* feat_b    = (const float*)d_in[15];
    const float* head_W1   = (const float*)d_in[16];
    const float* head_b1   = (const float*)d_in[17];
    const float* head_W2   = (const float*)d_in[18];
    const float* head_b2   = (const float*)d_in[19];

    int N = in_sizes[0];
    int E = in_sizes[3];
    const int* rowp = edge_index;
    const int* colp = edge_index + E;

    float* out_hf   = (float*)d_out;
    float* out_pred = (float*)d_out + (size_t)NGR * FEAT;

    static int attr_done = 0;
    if (!attr_done) {
        cudaFuncSetAttribute(hmma_gemm_kernel,
                             cudaFuncAttributeMaxDynamicSharedMemorySize, GEMM_SMEM);
        attr_done = 1;
    }

    // node embeddings -> bf16 hi/lo planes (zero padding everywhere)
    embed_kernel<<<MPAD, 320>>>(atom_type, chirality, atom_emb1, atom_emb2, N);
    // W^T bf16 split for all layers
    conv_w_kernel<<<dim3(LD, NLAYER), LD>>>(W);

    // CSR by destination
    zero_deg_kernel<<<(N + 256) / 256, 256>>>(N);
    count_kernel<<<(E + 255) / 256, 256>>>(colp, E);
    scan1_kernel<<<NTILES, 1024>>>(N);
    scan2_kernel<<<1, 128>>>(NTILES, N);
    scan3_kernel<<<NTILES, 1024>>>(N);
    fill_kernel<<<(E + 255) / 256, 256>>>(rowp, colp, edge_type, edge_dir, E);

    for (int l = 0; l < NLAYER; l++) {
        hmma_gemm_kernel<<<dim3(LD / 64, MPAD / 128), 256, GEMM_SMEM>>>(l);
        zero_stats_kernel<<<2, 256>>>();
        aggstats_kernel<<<(N + 127) / 128, 320>>>(ee1 + l * 5, ee2 + l * 3,
                                                  b + (size_t)l * EMBD, N);
        int last = (l == NLAYER - 1);
        bnnorm_kernel<<<(N + 15) / 16, 320>>>(bn_gamma + (size_t)l * EMBD,
                                              bn_beta + (size_t)l * EMBD,
                                              N, last ? 0 : 1,
                                              last ? 1 : 0,   // fp32 only for pooling
                                              last ? 0 : 1);  // bf16 planes for next GEMM
    }

    // global mean pool
    zero_pool_kernel<<<(NGR * EMBD + 255) / 256, 256>>>();
    pool_kernel<<<(N + 127) / 128, 320>>>(batch, N);
    hg_kernel<<<NGR, 320>>>();

    // feature + head
    featgemm_kernel<<<NGR / 8, 256>>>(feat_W, feat_b, out_hf);
    head_kernel<<<NGR / 8, 128>>>(out_hf, head_W1, head_b1, head_W2, head_b2, out_pred);
}

// round 11
// speedup vs baseline: 1.1628x; 1.1628x over previous
#include <cuda_runtime.h>
#include <cuda_bf16.h>
#include <math.h>
#include <stdint.h>

// ---------------- problem constants ----------------
#define NNODES   100000
#define NEDGES   200000
#define EMBD     300
#define LD       320            // padded feature stride (K and N pad)
#define MPAD     100096         // 782 * 128
#define NGR      4096
#define FEAT     256
#define HFEAT    128
#define NLAYER   5
#define NTILES   98             // ceil(NNODES/1024)

// ---------------- device scratch ----------------
__device__ float g_out[(size_t)MPAD * LD];    // GEMM output / embed h (fp32)
__device__ __align__(16) __nv_bfloat16 g_hbf_hi[(size_t)MPAD * LD];  // agg output, bf16 hi
__device__ __align__(16) __nv_bfloat16 g_hbf_lo[(size_t)MPAD * LD];  // agg output, bf16 lo
__device__ __align__(16) __nv_bfloat16 g_wt_hi[NLAYER * LD * LD];    // W^T bf16 split [l][n][k]
__device__ __align__(16) __nv_bfloat16 g_wt_lo[NLAYER * LD * LD];
__device__ float g_colsum[LD];
__device__ float g_colsq[LD];
__device__ float g_scale[LD];
__device__ float g_shift[LD];
__device__ float g_bpad[LD];
__device__ float g_esum[(size_t)NLAYER * MPAD];
__device__ int   g_deg[NNODES + 1];
__device__ int   g_rowptr[NNODES + 1];
__device__ int   g_cursor[NNODES];
__device__ int   g_entries[NEDGES];
__device__ int   g_tilesum[NTILES];
__device__ int   g_tileoff[NTILES];
__device__ float g_sums[NGR * EMBD];
__device__ int   g_counts[NGR];
__device__ float g_hg[NGR * EMBD];

// ---------------- helpers ----------------
__device__ __forceinline__ uint32_t smem_u32(const void* p) {
    uint32_t a;
    asm("{ .reg .u64 t; cvta.to.shared.u64 t, %1; cvt.u32.u64 %0, t; }" : "=r"(a) : "l"(p));
    return a;
}

static __device__ __forceinline__ void split_bf16(float x, __nv_bfloat16& hi, __nv_bfloat16& lo) {
    hi = __float2bfloat16(x);
    lo = __float2bfloat16(x - __bfloat162float(hi));
}

__device__ __forceinline__ void ldsm_x4(uint32_t addr, uint32_t* r) {
    asm volatile("ldmatrix.sync.aligned.m8n8.x4.shared.b16 {%0,%1,%2,%3}, [%4];"
                 : "=r"(r[0]), "=r"(r[1]), "=r"(r[2]), "=r"(r[3]) : "r"(addr));
}

__device__ __forceinline__ void mma16816(float* c, const uint32_t* a, const uint32_t* b) {
    asm volatile(
        "mma.sync.aligned.m16n8k16.row.col.f32.bf16.bf16.f32 "
        "{%0,%1,%2,%3}, {%4,%5,%6,%7}, {%8,%9}, {%0,%1,%2,%3};"
        : "+f"(c[0]), "+f"(c[1]), "+f"(c[2]), "+f"(c[3])
        : "r"(a[0]), "r"(a[1]), "r"(a[2]), "r"(a[3]), "r"(b[0]), "r"(b[1]));
}

#define CP16(dst, src) \
    asm volatile("cp.async.cg.shared.global [%0], [%1], 16;" :: "r"(dst), "l"(src))
#define CP_COMMIT() asm volatile("cp.async.commit_group;")
#define CP_WAIT0()  asm volatile("cp.async.wait_group 0;")

// ---------------- embed: g_out = emb1[at] + emb2[ch]; also zero deg ----------------
__global__ void embed_kernel(const int* __restrict__ at, const int* __restrict__ ch,
                             const float* __restrict__ e1, const float* __restrict__ e2,
                             int N) {
    int r = blockIdx.x;              // 0..N-1
    int f = threadIdx.x;             // 0..319
    if (f == 0) g_deg[r] = 0;
    float v = 0.f;
    if (f < EMBD) {
        v = e1[(size_t)at[r] * EMBD + f] + e2[(size_t)ch[r] * EMBD + f];
    }
    g_out[(size_t)r * LD + f] = v;
}

// ---------------- W^T bf16 split: wt[l][n][k] = split(W[l][k][n]) ----------------
__global__ void conv_w_kernel(const float* __restrict__ W) {
    int n = blockIdx.x, l = blockIdx.y, k = threadIdx.x;   // 320 x 5, 320 threads
    float v = (n < EMBD && k < EMBD) ? W[((size_t)l * EMBD + k) * EMBD + n] : 0.f;
    __nv_bfloat16 hi, lo;
    split_bf16(v, hi, lo);
    size_t idx = ((size_t)l * LD + n) * LD + k;
    g_wt_hi[idx] = hi;
    g_wt_lo[idx] = lo;
}

// ---------------- CSR build ----------------
__global__ void count_kernel(const int* __restrict__ colp, int E) {
    int e = blockIdx.x * blockDim.x + threadIdx.x;
    if (e < E) atomicAdd(&g_deg[colp[e]], 1);
}
__global__ void scan1_kernel(int N) {
    __shared__ int ws[32];
    int tid = threadIdx.x, lane = tid & 31, w = tid >> 5;
    int i = blockIdx.x * 1024 + tid;
    int v = (i < N) ? g_deg[i] : 0;
    int x = v;
    #pragma unroll
    for (int o = 1; o < 32; o <<= 1) {
        int y = __shfl_up_sync(0xFFFFFFFFu, x, o);
        if (lane >= o) x += y;
    }
    if (lane == 31) ws[w] = x;
    __syncthreads();
    if (w == 0) {
        int t = ws[lane];
        #pragma unroll
        for (int o = 1; o < 32; o <<= 1) {
            int y = __shfl_up_sync(0xFFFFFFFFu, t, o);
            if (lane >= o) t += y;
        }
        ws[lane] = t;
    }
    __syncthreads();
    int incl = x + (w ? ws[w - 1] : 0);
    if (i < N) g_rowptr[i] = incl - v;
    if (tid == 1023) g_tilesum[blockIdx.x] = incl;
}
__global__ void scan2_kernel(int T, int N) {
    __shared__ int ws[4];
    int tid = threadIdx.x, lane = tid & 31, w = tid >> 5;   // 128 threads
    int v = (tid < T) ? g_tilesum[tid] : 0;
    int x = v;
    #pragma unroll
    for (int o = 1; o < 32; o <<= 1) {
        int y = __shfl_up_sync(0xFFFFFFFFu, x, o);
        if (lane >= o) x += y;
    }
    if (lane == 31) ws[w] = x;
    __syncthreads();
    int add = 0;
    for (int j = 0; j < w; j++) add += ws[j];
    int incl = x + add;
    if (tid < T) g_tileoff[tid] = incl - v;
    if (tid == T - 1) g_rowptr[N] = incl;
}
__global__ void scan3_kernel(int N) {
    int i = blockIdx.x * 1024 + threadIdx.x;
    if (i < N) {
        int v = g_rowptr[i] + g_tileoff[blockIdx.x];
        g_rowptr[i] = v;
        g_cursor[i] = v;
    }
}
__global__ void fill_kernel(const int* __restrict__ rowp, const int* __restrict__ colp,
                            const int* __restrict__ et, const int* __restrict__ ed, int E) {
    int e = blockIdx.x * blockDim.x + threadIdx.x;
    if (e >= E) return;
    int c = colp[e];
    int pos = atomicAdd(&g_cursor[c], 1);
    g_entries[pos] = rowp[e] | (et[e] << 20) | (ed[e] << 23);
}

// ---------------- esum for all layers: esum[l][v] = self + sum_in (ee1+ee2) ----------------
__global__ void esum_kernel(const float* __restrict__ ee1, const float* __restrict__ ee2,
                            int N) {
    int v = blockIdx.x * 1024 + threadIdx.x;
    int l = blockIdx.y;
    if (v >= MPAD) return;
    float s = 0.f;
    if (v < N) {
        const float* e1 = ee1 + l * 5;
        const float* e2 = ee2 + l * 3;
        s = e1[4] + e2[0];
        int st = g_rowptr[v], en = g_rowptr[v + 1];
        for (int i = st; i < en; i++) {
            int p = g_entries[i];
            s += e1[(p >> 20) & 7] + e2[(p >> 23) & 3];
        }
    }
    g_esum[(size_t)l * MPAD + v] = s;
}

// ---------------- BN params: scale/shift for agg-of-layer-l, zero stats, pad b ----------------
// l==0: identity (embed input). l>=1: from stats of layer l-1, gamma/beta[l-1].
__global__ void bnparam_kernel(const float* __restrict__ gamma, const float* __restrict__ beta,
                               const float* __restrict__ b, int l, int N) {
    int f = threadIdx.x;   // 0..319
    float sc = 0.f, sh = 0.f;
    if (f < EMBD) {
        if (l == 0) {
            sc = 1.f;
        } else {
            float invN = 1.0f / (float)N;
            float m = g_colsum[f] * invN;
            float var = g_colsq[f] * invN - m * m;
            float g = gamma[(size_t)(l - 1) * EMBD + f];
            float bt = beta[(size_t)(l - 1) * EMBD + f];
            sc = g * rsqrtf(var + 1e-5f);
            sh = bt - m * sc;
        }
    }
    g_scale[f] = sc;
    g_shift[f] = sh;
    g_colsum[f] = 0.f;
    g_colsq[f] = 0.f;
    if (l < NLAYER) g_bpad[f] = (f < EMBD) ? b[(size_t)l * EMBD + f] : 0.f;
}

// ---------------- aggregation with BN(+relu) applied on read; writes bf16 planes ----------------
__global__ __launch_bounds__(320) void agg_kernel(int relu, int N) {
    int f = threadIdx.x;
    float sc = g_scale[f], sh = g_shift[f];
    int r0 = blockIdx.x * 128;
    int rend = min(r0 + 128, MPAD);
    for (int r = r0; r < rend; r++) {
        float a = 0.f;
        if (r < N) {
            float x = g_out[(size_t)r * LD + f];
            a = fmaf(x, sc, sh);
            if (relu) a = fmaxf(a, 0.f);
            int st = g_rowptr[r], en = g_rowptr[r + 1];
            for (int i = st; i < en; i++) {
                int src = g_entries[i] & 0xFFFFF;
                float xs = g_out[(size_t)src * LD + f];
                float as = fmaf(xs, sc, sh);
                if (relu) as = fmaxf(as, 0.f);
                a += as;
            }
        }
        __nv_bfloat16 hi, lo;
        split_bf16(a, hi, lo);
        size_t idx = (size_t)r * LD + f;
        g_hbf_hi[idx] = hi;
        g_hbf_lo[idx] = lo;
    }
}

// ---------------- HMMA 3xBF16 GEMM + fused epilogue (+b +esum, BN stats) ----------------
// CTA tile 128x64, BK=32, 8 warps as 4(M)x2(N), warp tile 32x32.
#define ASTR 40
#define STAGE_B 30720
#define AH_OFF 0
#define AL_OFF 10240
#define BH_OFF 20480
#define BL_OFF 25600
#define GEMM_SMEM (2 * STAGE_B)

__global__ __launch_bounds__(256, 2) void hmma_gemm_kernel(int layer) {
    extern __shared__ __align__(16) char dsm[];
    __shared__ float s_cs[8][4][8], s_cq[8][4][8];
    uint32_t sbase = smem_u32(dsm);
    int tid = threadIdx.x, wid = tid >> 5, lane = tid & 31;
    int bm = blockIdx.y * 128, bn = blockIdx.x * 64;
    int wm = (wid & 3) * 32;
    int wn = (wid >> 2) * 32;

    const __nv_bfloat16* Ah = g_hbf_hi + (size_t)bm * LD;
    const __nv_bfloat16* Al = g_hbf_lo + (size_t)bm * LD;
    const __nv_bfloat16* Bh = g_wt_hi + ((size_t)layer * LD + bn) * LD;
    const __nv_bfloat16* Bl = g_wt_lo + ((size_t)layer * LD + bn) * LD;

    float acc[2][4][4];
    #pragma unroll
    for (int i = 0; i < 2; i++)
        #pragma unroll
        for (int j = 0; j < 4; j++)
            #pragma unroll
            for (int q = 0; q < 4; q++) acc[i][j][q] = 0.f;

    uint32_t aoff = (uint32_t)((wm + (lane & 15)) * ASTR + (lane >> 4) * 8) * 2;
    uint32_t boff = (uint32_t)((wn + (lane & 7) + ((lane >> 4) & 1) * 8) * ASTR +
                               ((lane >> 3) & 1) * 8) * 2;

    int ar0 = tid >> 2, ac = tid & 3;
    uint32_t a_so = (uint32_t)(ar0 * ASTR + ac * 8) * 2;
    uint32_t a_so1 = (uint32_t)((ar0 + 64) * ASTR + ac * 8) * 2;
    uint32_t b_so = a_so;

    #define GEMM_ISSUE(kc, s) do {                                              \
        uint32_t st_ = sbase + (s) * STAGE_B;                                   \
        int k0_ = (kc) * 32;                                                    \
        const __nv_bfloat16* pa0h = Ah + (size_t)ar0 * LD + k0_ + ac * 8;       \
        const __nv_bfloat16* pa0l = Al + (size_t)ar0 * LD + k0_ + ac * 8;       \
        const __nv_bfloat16* pa1h = pa0h + (size_t)64 * LD;                     \
        const __nv_bfloat16* pa1l = pa0l + (size_t)64 * LD;                     \
        const __nv_bfloat16* pbh  = Bh + (size_t)ar0 * LD + k0_ + ac * 8;       \
        const __nv_bfloat16* pbl  = Bl + (size_t)ar0 * LD + k0_ + ac * 8;       \
        CP16(st_ + AH_OFF + a_so,  pa0h);                                       \
        CP16(st_ + AL_OFF + a_so,  pa0l);                                       \
        CP16(st_ + AH_OFF + a_so1, pa1h);                                       \
        CP16(st_ + AL_OFF + a_so1, pa1l);                                       \
        CP16(st_ + BH_OFF + b_so,  pbh);                                        \
        CP16(st_ + BL_OFF + b_so,  pbl);                                        \
        CP_COMMIT();                                                            \
    } while (0)

    GEMM_ISSUE(0, 0);
    CP_WAIT0();
    __syncthreads();

    for (int kc = 0; kc < 10; kc++) {
        int cur = kc & 1;
        if (kc < 9) GEMM_ISSUE(kc + 1, cur ^ 1);
        uint32_t st = sbase + cur * STAGE_B;

        #pragma unroll
        for (int k16 = 0; k16 < 2; k16++) {
            uint32_t kb = (uint32_t)k16 * 32;
            uint32_t afh[2][4], afl[2][4];
            #pragma unroll
            for (int mi = 0; mi < 2; mi++) {
                uint32_t o = aoff + (uint32_t)(mi * 16 * ASTR) * 2 + kb;
                ldsm_x4(st + AH_OFF + o, afh[mi]);
                ldsm_x4(st + AL_OFF + o, afl[mi]);
            }
            uint32_t bfh[4][2], bfl[4][2];
            #pragma unroll
            for (int nj = 0; nj < 4; nj += 2) {
                uint32_t o = boff + (uint32_t)(nj * 8 * ASTR) * 2 + kb;
                uint32_t t[4];
                ldsm_x4(st + BH_OFF + o, t);
                bfh[nj][0] = t[0]; bfh[nj][1] = t[1];
                bfh[nj + 1][0] = t[2]; bfh[nj + 1][1] = t[3];
                ldsm_x4(st + BL_OFF + o, t);
                bfl[nj][0] = t[0]; bfl[nj][1] = t[1];
                bfl[nj + 1][0] = t[2]; bfl[nj + 1][1] = t[3];
            }
            #pragma unroll
            for (int mi = 0; mi < 2; mi++)
                #pragma unroll
                for (int ni = 0; ni < 4; ni++) {
                    mma16816(acc[mi][ni], afh[mi], bfh[ni]);
                    mma16816(acc[mi][ni], afh[mi], bfl[ni]);
                    mma16816(acc[mi][ni], afl[mi], bfh[ni]);
                }
        }
        if (kc < 9) CP_WAIT0();
        __syncthreads();
    }

    // ---- epilogue: out = acc + b + esum; write g_out; accumulate BN stats ----
    int qr = lane >> 2, qc = (lane & 3) * 2;
    const float* es = g_esum + (size_t)layer * MPAD;
    float bv[4][2];
    #pragma unroll
    for (int ni = 0; ni < 4; ni++) {
        bv[ni][0] = g_bpad[bn + wn + ni * 8 + qc];
        bv[ni][1] = g_bpad[bn + wn + ni * 8 + qc + 1];
    }
    float cs[8], cq[8];
    #pragma unroll
    for (int j = 0; j < 8; j++) { cs[j] = 0.f; cq[j] = 0.f; }

    #pragma unroll
    for (int mi = 0; mi < 2; mi++) {
        int row0 = bm + wm + mi * 16 + qr;
        float e0 = es[row0], e1 = es[row0 + 8];
        bool gd0 = row0 < NNODES, gd1 = (row0 + 8) < NNODES;
        #pragma unroll
        for (int ni = 0; ni < 4; ni++) {
            int col = bn + wn + ni * 8 + qc;
            float v0 = acc[mi][ni][0] + bv[ni][0] + e0;
            float v1 = acc[mi][ni][1] + bv[ni][1] + e0;
            float v2 = acc[mi][ni][2] + bv[ni][0] + e1;
            float v3 = acc[mi][ni][3] + bv[ni][1] + e1;
            float2 o0; o0.x = v0; o0.y = v1;
            float2 o1; o1.x = v2; o1.y = v3;
            *(float2*)&g_out[(size_t)row0 * LD + col] = o0;
            *(float2*)&g_out[(size_t)(row0 + 8) * LD + col] = o1;
            if (gd0) { cs[ni * 2] += v0; cq[ni * 2] += v0 * v0;
                       cs[ni * 2 + 1] += v1; cq[ni * 2 + 1] += v1 * v1; }
            if (gd1) { cs[ni * 2] += v2; cq[ni * 2] += v2 * v2;
                       cs[ni * 2 + 1] += v3; cq[ni * 2 + 1] += v3 * v3; }
        }
    }
    // reduce over the 8 qr-lane groups (lanes sharing lane&3)
    #pragma unroll
    for (int o = 4; o < 32; o <<= 1) {
        #pragma unroll
        for (int j = 0; j < 8; j++) {
            cs[j] += __shfl_xor_sync(0xFFFFFFFFu, cs[j], o);
            cq[j] += __shfl_xor_sync(0xFFFFFFFFu, cq[j], o);
        }
    }
    if (lane < 4) {
        #pragma unroll
        for (int j = 0; j < 8; j++) {
            s_cs[wid][lane][j] = cs[j];
            s_cq[wid][lane][j] = cq[j];
        }
    }
    __syncthreads();
    if (tid < 64) {
        int c = tid;
        int wg = c >> 5, ni = (c & 31) >> 3, qlo = (c & 7) >> 1, q = c & 1;
        int j = ni * 2 + q;
        float S = 0.f, Q = 0.f;
        #pragma unroll
        for (int w = 0; w < 4; w++) {
            S += s_cs[wg * 4 + w][qlo][j];
            Q += s_cq[wg * 4 + w][qlo][j];
        }
        atomicAdd(&g_colsum[bn + c], S);
        atomicAdd(&g_colsq[bn + c], Q);
    }
}

// ---------------- pooling (run-length accumulate, batch is sorted) ----------------
__global__ void zero_pool_kernel() {
    int i = blockIdx.x * blockDim.x + threadIdx.x;
    if (i < NGR * EMBD) g_sums[i] = 0.f;
    if (i < NGR) g_counts[i] = 0;
}
__global__ __launch_bounds__(320) void pool_kernel(const int* __restrict__ batch, int N) {
    int f = threadIdx.x;
    int r0 = blockIdx.x * 128;
    int rend = min(r0 + 128, N);
    if (r0 >= N) return;
    int curg = batch[r0];
    float acc = 0.f;
    int cnt = 0;
    for (int r = r0; r < rend; r++) {
        int g = batch[r];
        if (g != curg) {
            if (f < EMBD) atomicAdd(&g_sums[(size_t)curg * EMBD + f], acc);
            if (f == EMBD) atomicAdd(&g_counts[curg], cnt);
            curg = g; acc = 0.f; cnt = 0;
        }
        if (f < EMBD) acc += g_out[(size_t)r * LD + f];
        cnt++;
    }
    if (f < EMBD) atomicAdd(&g_sums[(size_t)curg * EMBD + f], acc);
    if (f == EMBD) atomicAdd(&g_counts[curg], cnt);
}
// hg = scale * (sum/cnt) + shift   (final BN applied post-pool; no relu)
__global__ __launch_bounds__(320) void hg_kernel() {
    int g = blockIdx.x;
    int t = threadIdx.x;
    if (t >= EMBD) return;
    float cnt = fmaxf((float)g_counts[g], 1.0f);
    g_hg[(size_t)g * EMBD + t] = fmaf(g_sums[(size_t)g * EMBD + t] / cnt,
                                     g_scale[t], g_shift[t]);
}

// ---------------- hf = hg @ feat_W + feat_b ----------------
__global__ __launch_bounds__(256) void featgemm_kernel(
        const float* __restrict__ fw, const float* __restrict__ fb,
        float* __restrict__ hf) {
    __shared__ __align__(16) float s[8 * EMBD];
    int g0 = blockIdx.x * 8;
    int j = threadIdx.x;  // 0..255
    for (int idx = j; idx < 8 * EMBD; idx += 256)
        s[idx] = g_hg[(size_t)g0 * EMBD + idx];
    __syncthreads();
    float acc[8];
    float bb = fb[j];
    #pragma unroll
    for (int i = 0; i < 8; i++) acc[i] = bb;
    for (int k = 0; k < EMBD; k++) {
        float w = fw[k * FEAT + j];
        #pragma unroll
        for (int i = 0; i < 8; i++) acc[i] = fmaf(s[i * EMBD + k], w, acc[i]);
    }
    #pragma unroll
    for (int i = 0; i < 8; i++)
        hf[(size_t)(g0 + i) * FEAT + j] = acc[i];
}

// ---------------- head: pred = softplus(hf@W1+b1)@W2 + b2 ----------------
__device__ __forceinline__ float softplus_f(float x) {
    return fmaxf(x, 0.f) + log1pf(expf(-fabsf(x)));
}
__global__ __launch_bounds__(128) void head_kernel(
        const float* __restrict__ hf,
        const float* __restrict__ W1, const float* __restrict__ b1,
        const float* __restrict__ W2, const float* __restrict__ b2,
        float* __restrict__ pred) {
    __shared__ __align__(16) float s[8 * FEAT];
    __shared__ float redA[8][4], redB[8][4];
    int g0 = blockIdx.x * 8;
    int j = threadIdx.x;  // 0..127
    for (int idx = j; idx < 8 * FEAT; idx += 128)
        s[idx] = hf[(size_t)g0 * FEAT + idx];
    __syncthreads();
    float acc[8];
    float bb = b1[j];
    #pragma unroll
    for (int i = 0; i < 8; i++) acc[i] = bb;
    for (int k = 0; k < FEAT; k++) {
        float w = W1[k * HFEAT + j];
        #pragma unroll
        for (int i = 0; i < 8; i++) acc[i] = fmaf(s[i * FEAT + k], w, acc[i]);
    }
    float w0 = W2[j * 2], w1 = W2[j * 2 + 1];
    int lane = j & 31, wid = j >> 5;
    #pragma unroll
    for (int i = 0; i < 8; i++) {
        float tv = softplus_f(acc[i]);
        float v0 = tv * w0, v1 = tv * w1;
        #pragma unroll
        for (int off = 16; off > 0; off >>= 1) {
            v0 += __shfl_down_sync(0xFFFFFFFFu, v0, off);
            v1 += __shfl_down_sync(0xFFFFFFFFu, v1, off);
        }
        if (lane == 0) { redA[i][wid] = v0; redB[i][wid] = v1; }
    }
    __syncthreads();
    if (j < 8) {
        float p0 = redA[j][0] + redA[j][1] + redA[j][2] + redA[j][3] + b2[0];
        float p1 = redB[j][0] + redB[j][1] + redB[j][2] + redB[j][3] + b2[1];
        pred[(size_t)(g0 + j) * 2 + 0] = p0;
        pred[(size_t)(g0 + j) * 2 + 1] = p1;
    }
}

// ---------------- launch ----------------
extern "C" void kernel_launch(void* const* d_in, const int* in_sizes, int n_in,
                              void* d_out, int out_size) {
    const int*   atom_type = (const int*)d_in[0];
    const int*   chirality = (const int*)d_in[1];
    const int*   edge_index = (const int*)d_in[2];
    const int*   edge_type = (const int*)d_in[3];
    const int*   edge_dir  = (const int*)d_in[4];
    const int*   batch     = (const int*)d_in[5];
    const float* atom_emb1 = (const float*)d_in[6];
    const float* atom_emb2 = (const float*)d_in[7];
    const float* W         = (const float*)d_in[8];
    const float* b         = (const float*)d_in[9];
    const float* ee1       = (const float*)d_in[10];
    const float* ee2       = (const float*)d_in[11];
    const float* bn_gamma  = (const float*)d_in[12];
    const float* bn_beta   = (const float*)d_in[13];
    const float* feat_W    = (const float*)d_in[14];
    const float* feat_b    = (const float*)d_in[15];
    const float* head_W1   = (const float*)d_in[16];
    const float* head_b1   = (const float*)d_in[17];
    const float* head_W2   = (const float*)d_in[18];
    const float* head_b2   = (const float*)d_in[19];

    int N = in_sizes[0];
    int E = in_sizes[3];
    const int* rowp = edge_index;
    const int* colp = edge_index + E;

    float* out_hf   = (float*)d_out;
    float* out_pred = (float*)d_out + (size_t)NGR * FEAT;

    static int attr_done = 0;
    if (!attr_done) {
        cudaFuncSetAttribute(hmma_gemm_kernel,
                             cudaFuncAttributeMaxDynamicSharedMemorySize, GEMM_SMEM);
        attr_done = 1;
    }

    // h0 -> g_out (fp32), zero degrees
    embed_kernel<<<N, 320>>>(atom_type, chirality, atom_emb1, atom_emb2, N);
    // W^T bf16 split for all layers
    conv_w_kernel<<<dim3(LD, NLAYER), LD>>>(W);

    // CSR by destination
    count_kernel<<<(E + 255) / 256, 256>>>(colp, E);
    scan1_kernel<<<NTILES, 1024>>>(N);
    scan2_kernel<<<1, 128>>>(NTILES, N);
    scan3_kernel<<<NTILES, 1024>>>(N);
    fill_kernel<<<(E + 255) / 256, 256>>>(rowp, colp, edge_type, edge_dir, E);

    // per-node scalar edge sums for all layers
    esum_kernel<<<dim3((MPAD + 1023) / 1024, NLAYER), 1024>>>(ee1, ee2, N);

    for (int l = 0; l < NLAYER; l++) {
        bnparam_kernel<<<1, 320>>>(bn_gamma, bn_beta, b, l, N);
        agg_kernel<<<MPAD / 128, 320>>>(l > 0 ? 1 : 0, N);
        hmma_gemm_kernel<<<dim3(LD / 64, MPAD / 128), 256, GEMM_SMEM>>>(l);
    }
    // final BN params (stats of layer 4, gamma/beta[4]); applied post-pool in hg
    bnparam_kernel<<<1, 320>>>(bn_gamma, bn_beta, b, NLAYER, N);

    // global mean pool on raw out_4, BN applied in hg
    zero_pool_kernel<<<(NGR * EMBD + 255) / 256, 256>>>();
    pool_kernel<<<(N + 127) / 128, 320>>>(batch, N);
    hg_kernel<<<NGR, 320>>>();

    // feature + head
    featgemm_kernel<<<NGR / 8, 256>>>(feat_W, feat_b, out_hf);
    head_kernel<<<NGR / 8, 128>>>(out_hf, head_W1, head_b1, head_W2, head_b2, out_pred);
}